// round 1
// baseline (speedup 1.0000x reference)
#include <cuda_runtime.h>
#include <math.h>

// ---------------------------------------------------------------------------
// Scratch (no allocs allowed -> __device__ globals)
// ---------------------------------------------------------------------------
#define T_TOK (4 * 2048)      // 8192 tokens
#define EMB   512
#define HEADS 8
#define HDIM  64
#define SEQ   2048

__device__ float g_q[T_TOK * EMB];
__device__ float g_k[T_TOK * EMB];
__device__ float g_v[T_TOK * EMB];
__device__ float g_h[T_TOK * 1024];   // MLP hidden (512 or 1024 wide)
__device__ float g_ctx[T_TOK * EMB];  // attention out, later reused for FFN out
__device__ float g_x[T_TOK * EMB];    // LN1 output

// ---------------------------------------------------------------------------
// Generic tiled fp32 GEMM: C[M,N] = A[M,K] @ B[K,N] + bias, optional relu
// BM=BN=64, BK=16, 256 threads, 4x4 micro-tile per thread.
// ---------------------------------------------------------------------------
#define BM 64
#define BN 64
#define BK 16

__global__ void gemm_kernel(const float* __restrict__ A, const float* __restrict__ B,
                            const float* __restrict__ bias, float* __restrict__ C,
                            int M, int N, int K, int relu)
{
    __shared__ float As[BK][BM + 1];
    __shared__ float Bs[BK][BN + 1];

    const int bm = blockIdx.y * BM;
    const int bn = blockIdx.x * BN;
    const int tid = threadIdx.x;          // 256
    const int tx = tid & 15;
    const int ty = tid >> 4;

    float acc[4][4];
#pragma unroll
    for (int i = 0; i < 4; i++)
#pragma unroll
        for (int j = 0; j < 4; j++) acc[i][j] = 0.f;

    for (int k0 = 0; k0 < K; k0 += BK) {
#pragma unroll
        for (int i = 0; i < 4; i++) {               // A tile: 64x16
            int idx = tid + i * 256;
            int r = idx >> 4, c = idx & 15;
            As[c][r] = A[(size_t)(bm + r) * K + k0 + c];
        }
#pragma unroll
        for (int i = 0; i < 4; i++) {               // B tile: 16x64
            int idx = tid + i * 256;
            int r = idx >> 6, c = idx & 63;
            Bs[r][c] = B[(size_t)(k0 + r) * N + bn + c];
        }
        __syncthreads();

#pragma unroll
        for (int kk = 0; kk < BK; kk++) {
            float a[4], b[4];
#pragma unroll
            for (int i = 0; i < 4; i++) a[i] = As[kk][ty * 4 + i];
#pragma unroll
            for (int j = 0; j < 4; j++) b[j] = Bs[kk][tx * 4 + j];
#pragma unroll
            for (int i = 0; i < 4; i++)
#pragma unroll
                for (int j = 0; j < 4; j++) acc[i][j] += a[i] * b[j];
        }
        __syncthreads();
    }

#pragma unroll
    for (int i = 0; i < 4; i++) {
        int r = bm + ty * 4 + i;
#pragma unroll
        for (int j = 0; j < 4; j++) {
            int c = bn + tx * 4 + j;
            float v = acc[i][j] + bias[c];
            if (relu) v = fmaxf(v, 0.f);
            C[(size_t)r * N + c] = v;
        }
    }
}

// ---------------------------------------------------------------------------
// Flash attention (non-causal), fp32. One block per (q-tile 64, head, batch).
// Q/K/V layout: [8192, 512] row-major, head h occupies cols [h*64, h*64+64).
// Online softmax with scale = 1/sqrt(512).
// ---------------------------------------------------------------------------
#define FQ 64
#define FK 64
#define FPAD 65
#define FLASH_SMEM (4 * FQ * FPAD * (int)sizeof(float))  // Qs,Ks,Vs,Ps

__global__ void flash_kernel(const float* __restrict__ Q, const float* __restrict__ K,
                             const float* __restrict__ V, float* __restrict__ O)
{
    extern __shared__ float smem[];
    float (*Qs)[FPAD] = (float (*)[FPAD])(smem);
    float (*Ks)[FPAD] = (float (*)[FPAD])(smem + FQ * FPAD);
    float (*Vs)[FPAD] = (float (*)[FPAD])(smem + 2 * FQ * FPAD);
    float (*Ps)[FPAD] = (float (*)[FPAD])(smem + 3 * FQ * FPAD);

    const int qt = blockIdx.x, h = blockIdx.y, b = blockIdx.z;
    const int tid = threadIdx.x;
    const int tx = tid & 15, ty = tid >> 4;
    const int rowbase = b * SEQ;
    const int colbase = h * HDIM;
    const float scale = 0.044194173824159216f;  // 1/sqrt(512)

    // Load Q tile [64,64]
#pragma unroll
    for (int i = 0; i < 16; i++) {
        int idx = tid + i * 256;
        int r = idx >> 6, c = idx & 63;
        Qs[r][c] = Q[(size_t)(rowbase + qt * FQ + r) * EMB + colbase + c];
    }

    float m[4], l[4], o[4][4];
#pragma unroll
    for (int i = 0; i < 4; i++) {
        m[i] = -1e30f; l[i] = 0.f;
#pragma unroll
        for (int j = 0; j < 4; j++) o[i][j] = 0.f;
    }

    for (int kt = 0; kt < SEQ / FK; kt++) {
        __syncthreads();  // protect Ks/Vs from previous iteration's PV read
#pragma unroll
        for (int i = 0; i < 16; i++) {
            int idx = tid + i * 256;
            int r = idx >> 6, c = idx & 63;
            size_t gr = (size_t)(rowbase + kt * FK + r) * EMB + colbase + c;
            Ks[r][c] = K[gr];
            Vs[r][c] = V[gr];
        }
        __syncthreads();

        // S = Q K^T  (4x4 per thread)
        float s[4][4];
#pragma unroll
        for (int i = 0; i < 4; i++)
#pragma unroll
            for (int j = 0; j < 4; j++) s[i][j] = 0.f;
#pragma unroll 8
        for (int kk = 0; kk < HDIM; kk++) {
            float a[4], bb[4];
#pragma unroll
            for (int i = 0; i < 4; i++) a[i] = Qs[ty * 4 + i][kk];
#pragma unroll
            for (int j = 0; j < 4; j++) bb[j] = Ks[tx * 4 + j][kk];
#pragma unroll
            for (int i = 0; i < 4; i++)
#pragma unroll
                for (int j = 0; j < 4; j++) s[i][j] += a[i] * bb[j];
        }
#pragma unroll
        for (int i = 0; i < 4; i++)
#pragma unroll
            for (int j = 0; j < 4; j++) s[i][j] *= scale;

        // online softmax per row (rows owned by 16 threads sharing ty)
#pragma unroll
        for (int i = 0; i < 4; i++) {
            float v = fmaxf(fmaxf(s[i][0], s[i][1]), fmaxf(s[i][2], s[i][3]));
#pragma unroll
            for (int off = 8; off; off >>= 1)
                v = fmaxf(v, __shfl_xor_sync(0xffffffffu, v, off, 16));
            float mn = fmaxf(m[i], v);
            float f = __expf(m[i] - mn);
            float rs = 0.f;
#pragma unroll
            for (int j = 0; j < 4; j++) {
                float p = __expf(s[i][j] - mn);
                Ps[ty * 4 + i][tx * 4 + j] = p;
                rs += p;
            }
#pragma unroll
            for (int off = 8; off; off >>= 1)
                rs += __shfl_xor_sync(0xffffffffu, rs, off, 16);
            l[i] = l[i] * f + rs;
            m[i] = mn;
#pragma unroll
            for (int j = 0; j < 4; j++) o[i][j] *= f;
        }
        __syncthreads();

        // O += P @ V
#pragma unroll 8
        for (int c = 0; c < FK; c++) {
            float p[4], vv[4];
#pragma unroll
            for (int i = 0; i < 4; i++) p[i] = Ps[ty * 4 + i][c];
#pragma unroll
            for (int j = 0; j < 4; j++) vv[j] = Vs[c][tx * 4 + j];
#pragma unroll
            for (int i = 0; i < 4; i++)
#pragma unroll
                for (int j = 0; j < 4; j++) o[i][j] += p[i] * vv[j];
        }
    }

#pragma unroll
    for (int i = 0; i < 4; i++) {
        float inv = 1.f / l[i];
        int r = rowbase + qt * FQ + ty * 4 + i;
#pragma unroll
        for (int j = 0; j < 4; j++)
            O[(size_t)r * EMB + colbase + tx * 4 + j] = o[i][j] * inv;
    }
}

// ---------------------------------------------------------------------------
// Fused residual + LayerNorm: out = LN(a + b) * g + beta. One block per row.
// ---------------------------------------------------------------------------
__global__ void ln_kernel(const float* __restrict__ A, const float* __restrict__ Bres,
                          const float* __restrict__ g, const float* __restrict__ beta,
                          float* __restrict__ out)
{
    const int row = blockIdx.x;
    const int t = threadIdx.x;  // 512
    float v = A[(size_t)row * EMB + t] + Bres[(size_t)row * EMB + t];

    __shared__ float rsum[16], rsq[16];
    float s1 = v, s2 = v * v;
#pragma unroll
    for (int off = 16; off; off >>= 1) {
        s1 += __shfl_xor_sync(0xffffffffu, s1, off);
        s2 += __shfl_xor_sync(0xffffffffu, s2, off);
    }
    if ((t & 31) == 0) { rsum[t >> 5] = s1; rsq[t >> 5] = s2; }
    __syncthreads();
    if (t < 32) {
        s1 = (t < 16) ? rsum[t] : 0.f;
        s2 = (t < 16) ? rsq[t] : 0.f;
#pragma unroll
        for (int off = 8; off; off >>= 1) {
            s1 += __shfl_xor_sync(0xffffffffu, s1, off);
            s2 += __shfl_xor_sync(0xffffffffu, s2, off);
        }
        if (t == 0) { rsum[0] = s1; rsq[0] = s2; }
    }
    __syncthreads();
    float mu = rsum[0] * (1.f / EMB);
    float var = rsq[0] * (1.f / EMB) - mu * mu;
    float inv = rsqrtf(var + 1e-5f);
    out[(size_t)row * EMB + t] = (v - mu) * inv * g[t] + beta[t];
}

// ---------------------------------------------------------------------------
// Launch
// ---------------------------------------------------------------------------
extern "C" void kernel_launch(void* const* d_in, const int* in_sizes, int n_in,
                              void* d_out, int out_size)
{
    (void)in_sizes; (void)n_in; (void)out_size;

    const float* x_in = (const float*)d_in[0];
    const float* qW1 = (const float*)d_in[1];  const float* qb1 = (const float*)d_in[2];
    const float* qW2 = (const float*)d_in[3];  const float* qb2 = (const float*)d_in[4];
    const float* kW1 = (const float*)d_in[5];  const float* kb1 = (const float*)d_in[6];
    const float* kW2 = (const float*)d_in[7];  const float* kb2 = (const float*)d_in[8];
    const float* vW1 = (const float*)d_in[9];  const float* vb1 = (const float*)d_in[10];
    const float* vW2 = (const float*)d_in[11]; const float* vb2 = (const float*)d_in[12];
    const float* fW1 = (const float*)d_in[13]; const float* fb1 = (const float*)d_in[14];
    const float* fW2 = (const float*)d_in[15]; const float* fb2 = (const float*)d_in[16];
    const float* ln1g = (const float*)d_in[17]; const float* ln1b = (const float*)d_in[18];
    const float* ln2g = (const float*)d_in[19]; const float* ln2b = (const float*)d_in[20];
    float* out = (float*)d_out;

    float *pq, *pk, *pv, *ph, *pctx, *px;
    cudaGetSymbolAddress((void**)&pq, g_q);
    cudaGetSymbolAddress((void**)&pk, g_k);
    cudaGetSymbolAddress((void**)&pv, g_v);
    cudaGetSymbolAddress((void**)&ph, g_h);
    cudaGetSymbolAddress((void**)&pctx, g_ctx);
    cudaGetSymbolAddress((void**)&px, g_x);

    cudaFuncSetAttribute(flash_kernel, cudaFuncAttributeMaxDynamicSharedMemorySize, FLASH_SMEM);

    dim3 gN512(512 / BN, T_TOK / BM);   // (8, 128)
    dim3 gN1024(1024 / BN, T_TOK / BM); // (16, 128)

    // Q/K/V two-layer MLPs
    gemm_kernel<<<gN512, 256>>>(x_in, qW1, qb1, ph, T_TOK, 512, 256, 1);
    gemm_kernel<<<gN512, 256>>>(ph,   qW2, qb2, pq, T_TOK, 512, 512, 0);
    gemm_kernel<<<gN512, 256>>>(x_in, kW1, kb1, ph, T_TOK, 512, 256, 1);
    gemm_kernel<<<gN512, 256>>>(ph,   kW2, kb2, pk, T_TOK, 512, 512, 0);
    gemm_kernel<<<gN512, 256>>>(x_in, vW1, vb1, ph, T_TOK, 512, 256, 1);
    gemm_kernel<<<gN512, 256>>>(ph,   vW2, vb2, pv, T_TOK, 512, 512, 0);

    // Attention
    flash_kernel<<<dim3(SEQ / FQ, HEADS, 4), 256, FLASH_SMEM>>>(pq, pk, pv, pctx);

    // x = LN(ctx + q)
    ln_kernel<<<T_TOK, EMB>>>(pctx, pq, ln1g, ln1b, px);

    // FFN
    gemm_kernel<<<gN1024, 256>>>(px, fW1, fb1, ph, T_TOK, 1024, 512, 1);
    gemm_kernel<<<gN512,  256>>>(ph, fW2, fb2, pctx, T_TOK, 512, 1024, 0);

    // out = LN(x + ff)
    ln_kernel<<<T_TOK, EMB>>>(px, pctx, ln2g, ln2b, out);
}

// round 3
// speedup vs baseline: 2.5354x; 2.5354x over previous
#include <cuda_runtime.h>
#include <cuda_bf16.h>
#include <cstdint>
#include <math.h>

#define TOK 8192
#define EMB 512
#define SEQ 2048

// ---------------------------------------------------------------------------
// Scratch (__device__ globals: no allocs allowed)
// ---------------------------------------------------------------------------
__device__ float g_q[TOK * EMB];
__device__ float g_k[TOK * EMB];
__device__ float g_v[TOK * EMB];
__device__ float g_ctx[TOK * EMB];
__device__ float g_x[TOK * EMB];

// bf16 hi/lo activations
__device__ __nv_bfloat16 g_xh[TOK * 256], g_xl[TOK * 256];
__device__ __nv_bfloat16 g_ah[TOK * 1024], g_al[TOK * 1024];
__device__ __nv_bfloat16 g_bh[TOK * 512],  g_bl[TOK * 512];

// bf16 hi/lo transposed weights, stored [N][K]
__device__ __nv_bfloat16 g_w1h[3][512 * 256], g_w1l[3][512 * 256];
__device__ __nv_bfloat16 g_w2h[3][512 * 512], g_w2l[3][512 * 512];
__device__ __nv_bfloat16 g_f1h[1024 * 512],   g_f1l[1024 * 512];
__device__ __nv_bfloat16 g_f2h[512 * 1024],   g_f2l[512 * 1024];

// ---------------------------------------------------------------------------
// Family-portable PTX helpers (NO tcgen05 — compute_103 target rejects it)
// ---------------------------------------------------------------------------
__device__ __forceinline__ uint32_t smem_u32(const void* p) {
    uint32_t a;
    asm("{ .reg .u64 t; cvta.to.shared.u64 t, %1; cvt.u32.u64 %0, t; }" : "=r"(a) : "l"(p));
    return a;
}
__device__ __forceinline__ void cp16(uint32_t dst, const void* src) {
    asm volatile("cp.async.cg.shared.global [%0], [%1], 16;" :: "r"(dst), "l"(src) : "memory");
}
__device__ __forceinline__ void cp_commit() {
    asm volatile("cp.async.commit_group;" ::: "memory");
}
__device__ __forceinline__ void ldsm_x4(uint32_t* r, uint32_t addr) {
    asm volatile("ldmatrix.sync.aligned.m8n8.x4.shared.b16 {%0,%1,%2,%3}, [%4];"
                 : "=r"(r[0]), "=r"(r[1]), "=r"(r[2]), "=r"(r[3]) : "r"(addr));
}
__device__ __forceinline__ void mma16816(float* c, const uint32_t* a, const uint32_t* b) {
    asm volatile("mma.sync.aligned.m16n8k16.row.col.f32.bf16.bf16.f32 "
                 "{%0,%1,%2,%3}, {%4,%5,%6,%7}, {%8,%9}, {%0,%1,%2,%3};"
                 : "+f"(c[0]), "+f"(c[1]), "+f"(c[2]), "+f"(c[3])
                 : "r"(a[0]), "r"(a[1]), "r"(a[2]), "r"(a[3]), "r"(b[0]), "r"(b[1]));
}

// ---------------------------------------------------------------------------
// Precision-split kernels: fp32 -> hi/lo bf16
// ---------------------------------------------------------------------------
__global__ void split_k(const float* __restrict__ X, __nv_bfloat16* __restrict__ h,
                        __nv_bfloat16* __restrict__ l, int n) {
    int i = blockIdx.x * blockDim.x + threadIdx.x;
    if (i < n) {
        float v = X[i];
        __nv_bfloat16 hb = __float2bfloat16(v);
        h[i] = hb;
        l[i] = __float2bfloat16(v - __bfloat162float(hb));
    }
}
// W[K][N] fp32 -> hi/lo bf16 transposed [N][K]
__global__ void splitT_k(const float* __restrict__ W, __nv_bfloat16* __restrict__ h,
                         __nv_bfloat16* __restrict__ l, int K, int N) {
    int i = blockIdx.x * blockDim.x + threadIdx.x;
    if (i < K * N) {
        int k = i / N, n = i - k * N;
        float v = W[i];
        __nv_bfloat16 hb = __float2bfloat16(v);
        h[(size_t)n * K + k] = hb;
        l[(size_t)n * K + k] = __float2bfloat16(v - __bfloat162float(hb));
    }
}

// ---------------------------------------------------------------------------
// HMMA bf16x3 GEMM: C[8192,N] = A[8192,K] @ B^T (B stored [N][K], hi/lo bf16)
// CTA 128x128, BK=32, 8 warps (warp tile 64x32), cp.async double buffering.
// fp32 accumulate; epilogue adds bias, optional relu, writes fp32 and/or hi/lo.
// ---------------------------------------------------------------------------
#define KPAD 40                          // smem row pitch in bf16 elems (80B)
#define TILE_SM (128 * KPAD)             // elems per tile
#define STAGE_SM (4 * TILE_SM)           // Ah, Al, Bh, Bl
#define GSMEM (2 * STAGE_SM * 2)         // bytes = 81920

__global__ void __launch_bounds__(256) hmma_gemm(
    const __nv_bfloat16* __restrict__ Ah, const __nv_bfloat16* __restrict__ Al,
    const __nv_bfloat16* __restrict__ Bh, const __nv_bfloat16* __restrict__ Bl,
    const float* __restrict__ bias, float* __restrict__ Cf,
    __nv_bfloat16* __restrict__ Ch, __nv_bfloat16* __restrict__ Cl,
    int N, int K, int relu)
{
    extern __shared__ __nv_bfloat16 sm[];
    const uint32_t smb = smem_u32(sm);
    const int tid = threadIdx.x;
    const int wid = tid >> 5, lane = tid & 31;
    const int bm = blockIdx.y * 128, bn = blockIdx.x * 128;
    const int wm = (wid >> 2) * 64, wn = (wid & 3) * 32;

    float acc[4][4][4];
#pragma unroll
    for (int mt = 0; mt < 4; mt++)
#pragma unroll
        for (int nt = 0; nt < 4; nt++)
#pragma unroll
            for (int r = 0; r < 4; r++) acc[mt][nt][r] = 0.f;

    const int nch = K >> 5;

    auto issue_loads = [&](int ck, int s) {
        const size_t koff = (size_t)ck * 32;
        const __nv_bfloat16* srcs[4] = {
            Ah + (size_t)bm * K + koff, Al + (size_t)bm * K + koff,
            Bh + (size_t)bn * K + koff, Bl + (size_t)bn * K + koff };
#pragma unroll
        for (int t = 0; t < 4; t++) {
#pragma unroll
            for (int i = 0; i < 2; i++) {
                int idx = tid + i * 256;           // 0..511
                int r = idx >> 2, c16 = idx & 3;   // row, 16B chunk
                uint32_t dst = smb + (uint32_t)(s * STAGE_SM + t * TILE_SM + r * KPAD + c16 * 8) * 2;
                cp16(dst, srcs[t] + (size_t)r * K + c16 * 8);
            }
        }
        cp_commit();
    };

    issue_loads(0, 0);

    // ldmatrix lane addressing (constant per thread)
    const int arow = (lane & 15);
    const int acol8 = (lane >> 4) * 8;
    const int brow = ((lane >> 4) & 1) * 8 + (lane & 7);
    const int bcol8 = ((lane >> 3) & 1) * 8;

    for (int ck = 0; ck < nch; ck++) {
        const int s = ck & 1;
        if (ck + 1 < nch) {
            issue_loads(ck + 1, s ^ 1);
            asm volatile("cp.async.wait_group 1;" ::: "memory");
        } else {
            asm volatile("cp.async.wait_group 0;" ::: "memory");
        }
        __syncthreads();

        const uint32_t aH = smb + (uint32_t)(s * STAGE_SM + 0 * TILE_SM) * 2;
        const uint32_t aL = smb + (uint32_t)(s * STAGE_SM + 1 * TILE_SM) * 2;
        const uint32_t bH = smb + (uint32_t)(s * STAGE_SM + 2 * TILE_SM) * 2;
        const uint32_t bL = smb + (uint32_t)(s * STAGE_SM + 3 * TILE_SM) * 2;

#pragma unroll
        for (int k16 = 0; k16 < 2; k16++) {
            uint32_t fah[4][4], fal[4][4], fbh[2][4], fbl[2][4];
#pragma unroll
            for (int mt = 0; mt < 4; mt++) {
                uint32_t off = (uint32_t)((wm + mt * 16 + arow) * KPAD + k16 * 16 + acol8) * 2;
                ldsm_x4(fah[mt], aH + off);
                ldsm_x4(fal[mt], aL + off);
            }
#pragma unroll
            for (int p = 0; p < 2; p++) {
                uint32_t off = (uint32_t)((wn + p * 16 + brow) * KPAD + k16 * 16 + bcol8) * 2;
                ldsm_x4(fbh[p], bH + off);
                ldsm_x4(fbl[p], bL + off);
            }
#pragma unroll
            for (int mt = 0; mt < 4; mt++) {
#pragma unroll
                for (int nt = 0; nt < 4; nt++) {
                    const uint32_t* bh2 = &fbh[nt >> 1][(nt & 1) * 2];
                    const uint32_t* bl2 = &fbl[nt >> 1][(nt & 1) * 2];
                    mma16816(acc[mt][nt], fah[mt], bh2);
                    mma16816(acc[mt][nt], fah[mt], bl2);
                    mma16816(acc[mt][nt], fal[mt], bh2);
                }
            }
        }
        __syncthreads();   // before next issue overwrites buffer s^1
    }

    // Epilogue
    const int gid = lane >> 2, tig = lane & 3;
#pragma unroll
    for (int mt = 0; mt < 4; mt++) {
#pragma unroll
        for (int nt = 0; nt < 4; nt++) {
            const int c0 = bn + wn + nt * 8 + tig * 2;
            const float bb0 = __ldg(&bias[c0]), bb1 = __ldg(&bias[c0 + 1]);
#pragma unroll
            for (int half = 0; half < 2; half++) {
                const int r = bm + wm + mt * 16 + gid + half * 8;
                float v0 = acc[mt][nt][half * 2 + 0] + bb0;
                float v1 = acc[mt][nt][half * 2 + 1] + bb1;
                if (relu) { v0 = fmaxf(v0, 0.f); v1 = fmaxf(v1, 0.f); }
                const size_t gi = (size_t)r * N + c0;
                if (Cf) *reinterpret_cast<float2*>(Cf + gi) = make_float2(v0, v1);
                if (Ch) {
                    __nv_bfloat16 h0 = __float2bfloat16(v0);
                    __nv_bfloat16 h1 = __float2bfloat16(v1);
                    __nv_bfloat162 hh; hh.x = h0; hh.y = h1;
                    __nv_bfloat162 ll;
                    ll.x = __float2bfloat16(v0 - __bfloat162float(h0));
                    ll.y = __float2bfloat16(v1 - __bfloat162float(h1));
                    *reinterpret_cast<__nv_bfloat162*>(Ch + gi) = hh;
                    *reinterpret_cast<__nv_bfloat162*>(Cl + gi) = ll;
                }
            }
        }
    }
}

// ---------------------------------------------------------------------------
// Flash attention fp32 (non-causal), transposed-smem layout for float4 LDS.
// One block per (q-tile 64, head, batch). scale = 1/sqrt(512).
// ---------------------------------------------------------------------------
#define FP 68
#define QO 0
#define KO (64 * FP)
#define PO (2 * 64 * FP)
#define VO (3 * 64 * FP)
#define FLASH_SMEM (4 * 64 * FP * (int)sizeof(float))

__global__ void flash_kernel(const float* __restrict__ Q, const float* __restrict__ K,
                             const float* __restrict__ V, float* __restrict__ O)
{
    extern __shared__ float fsm[];
    const int qt = blockIdx.x, h = blockIdx.y, b = blockIdx.z;
    const int tid = threadIdx.x;          // 256
    const int tx = tid & 15, ty = tid >> 4;
    const int rowbase = b * SEQ;
    const int colbase = h * 64;
    const float scale = 0.044194173824159216f;

    {
        const float* Qb = Q + (size_t)(rowbase + qt * 64) * EMB + colbase;
#pragma unroll
        for (int i = 0; i < 4; i++) {
            int idx = tid + i * 256;
            int r = idx >> 4, c4 = (idx & 15) * 4;
            float4 q4 = *reinterpret_cast<const float4*>(Qb + (size_t)r * EMB + c4);
            fsm[QO + (c4 + 0) * FP + r] = q4.x;
            fsm[QO + (c4 + 1) * FP + r] = q4.y;
            fsm[QO + (c4 + 2) * FP + r] = q4.z;
            fsm[QO + (c4 + 3) * FP + r] = q4.w;
        }
    }

    float m[4], l[4], o[4][4];
#pragma unroll
    for (int i = 0; i < 4; i++) {
        m[i] = -1e30f; l[i] = 0.f;
#pragma unroll
        for (int j = 0; j < 4; j++) o[i][j] = 0.f;
    }

    for (int kt = 0; kt < SEQ / 64; kt++) {
        __syncthreads();
        {
            const float* Kb = K + (size_t)(rowbase + kt * 64) * EMB + colbase;
            const float* Vb = V + (size_t)(rowbase + kt * 64) * EMB + colbase;
#pragma unroll
            for (int i = 0; i < 4; i++) {
                int idx = tid + i * 256;
                int r = idx >> 4, c4 = (idx & 15) * 4;
                float4 k4 = *reinterpret_cast<const float4*>(Kb + (size_t)r * EMB + c4);
                fsm[KO + (c4 + 0) * FP + r] = k4.x;
                fsm[KO + (c4 + 1) * FP + r] = k4.y;
                fsm[KO + (c4 + 2) * FP + r] = k4.z;
                fsm[KO + (c4 + 3) * FP + r] = k4.w;
                float4 v4 = *reinterpret_cast<const float4*>(Vb + (size_t)r * EMB + c4);
                *reinterpret_cast<float4*>(&fsm[VO + r * FP + c4]) = v4;
            }
        }
        __syncthreads();

        float s[4][4];
#pragma unroll
        for (int i = 0; i < 4; i++)
#pragma unroll
            for (int j = 0; j < 4; j++) s[i][j] = 0.f;
#pragma unroll 8
        for (int kk = 0; kk < 64; kk++) {
            float4 a4 = *reinterpret_cast<const float4*>(&fsm[QO + kk * FP + ty * 4]);
            float4 b4 = *reinterpret_cast<const float4*>(&fsm[KO + kk * FP + tx * 4]);
            float a[4] = {a4.x, a4.y, a4.z, a4.w};
            float bb[4] = {b4.x, b4.y, b4.z, b4.w};
#pragma unroll
            for (int i = 0; i < 4; i++)
#pragma unroll
                for (int j = 0; j < 4; j++) s[i][j] += a[i] * bb[j];
        }

#pragma unroll
        for (int i = 0; i < 4; i++) {
#pragma unroll
            for (int j = 0; j < 4; j++) s[i][j] *= scale;
            float v = fmaxf(fmaxf(s[i][0], s[i][1]), fmaxf(s[i][2], s[i][3]));
#pragma unroll
            for (int off = 8; off; off >>= 1)
                v = fmaxf(v, __shfl_xor_sync(0xffffffffu, v, off, 16));
            float mn = fmaxf(m[i], v);
            float f = __expf(m[i] - mn);
            float rs = 0.f;
#pragma unroll
            for (int j = 0; j < 4; j++) {
                float p = __expf(s[i][j] - mn);
                fsm[PO + (tx * 4 + j) * FP + ty * 4 + i] = p;
                rs += p;
            }
#pragma unroll
            for (int off = 8; off; off >>= 1)
                rs += __shfl_xor_sync(0xffffffffu, rs, off, 16);
            l[i] = l[i] * f + rs;
            m[i] = mn;
#pragma unroll
            for (int j = 0; j < 4; j++) o[i][j] *= f;
        }
        __syncthreads();

#pragma unroll 8
        for (int c = 0; c < 64; c++) {
            float4 p4 = *reinterpret_cast<const float4*>(&fsm[PO + c * FP + ty * 4]);
            float4 v4 = *reinterpret_cast<const float4*>(&fsm[VO + c * FP + tx * 4]);
            float p[4] = {p4.x, p4.y, p4.z, p4.w};
            float vv[4] = {v4.x, v4.y, v4.z, v4.w};
#pragma unroll
            for (int i = 0; i < 4; i++)
#pragma unroll
                for (int j = 0; j < 4; j++) o[i][j] += p[i] * vv[j];
        }
    }

#pragma unroll
    for (int i = 0; i < 4; i++) {
        float inv = 1.f / l[i];
        int r = rowbase + qt * 64 + ty * 4 + i;
#pragma unroll
        for (int j = 0; j < 4; j++)
            O[(size_t)r * EMB + colbase + tx * 4 + j] = o[i][j] * inv;
    }
}

// ---------------------------------------------------------------------------
// Fused residual + LayerNorm
// ---------------------------------------------------------------------------
__global__ void ln_kernel(const float* __restrict__ A, const float* __restrict__ Bres,
                          const float* __restrict__ g, const float* __restrict__ beta,
                          float* __restrict__ out)
{
    const int row = blockIdx.x;
    const int t = threadIdx.x;  // 512
    float v = A[(size_t)row * EMB + t] + Bres[(size_t)row * EMB + t];

    __shared__ float rsum[16], rsq[16];
    float s1 = v, s2 = v * v;
#pragma unroll
    for (int off = 16; off; off >>= 1) {
        s1 += __shfl_xor_sync(0xffffffffu, s1, off);
        s2 += __shfl_xor_sync(0xffffffffu, s2, off);
    }
    if ((t & 31) == 0) { rsum[t >> 5] = s1; rsq[t >> 5] = s2; }
    __syncthreads();
    if (t < 32) {
        s1 = (t < 16) ? rsum[t] : 0.f;
        s2 = (t < 16) ? rsq[t] : 0.f;
#pragma unroll
        for (int off = 8; off; off >>= 1) {
            s1 += __shfl_xor_sync(0xffffffffu, s1, off);
            s2 += __shfl_xor_sync(0xffffffffu, s2, off);
        }
        if (t == 0) { rsum[0] = s1; rsq[0] = s2; }
    }
    __syncthreads();
    float mu = rsum[0] * (1.f / EMB);
    float var = rsq[0] * (1.f / EMB) - mu * mu;
    float inv = rsqrtf(var + 1e-5f);
    out[(size_t)row * EMB + t] = (v - mu) * inv * g[t] + beta[t];
}

// ---------------------------------------------------------------------------
// Launch
// ---------------------------------------------------------------------------
extern "C" void kernel_launch(void* const* d_in, const int* in_sizes, int n_in,
                              void* d_out, int out_size)
{
    (void)in_sizes; (void)n_in; (void)out_size;

    const float* x_in = (const float*)d_in[0];
    const float* W1[3] = {(const float*)d_in[1], (const float*)d_in[5], (const float*)d_in[9]};
    const float* b1[3] = {(const float*)d_in[2], (const float*)d_in[6], (const float*)d_in[10]};
    const float* W2[3] = {(const float*)d_in[3], (const float*)d_in[7], (const float*)d_in[11]};
    const float* b2[3] = {(const float*)d_in[4], (const float*)d_in[8], (const float*)d_in[12]};
    const float* fW1 = (const float*)d_in[13]; const float* fb1 = (const float*)d_in[14];
    const float* fW2 = (const float*)d_in[15]; const float* fb2 = (const float*)d_in[16];
    const float* ln1g = (const float*)d_in[17]; const float* ln1b = (const float*)d_in[18];
    const float* ln2g = (const float*)d_in[19]; const float* ln2b = (const float*)d_in[20];
    float* out = (float*)d_out;

    float *pq, *pk, *pv, *pctx, *px;
    cudaGetSymbolAddress((void**)&pq, g_q);
    cudaGetSymbolAddress((void**)&pk, g_k);
    cudaGetSymbolAddress((void**)&pv, g_v);
    cudaGetSymbolAddress((void**)&pctx, g_ctx);
    cudaGetSymbolAddress((void**)&px, g_x);
    __nv_bfloat16 *xh, *xl, *ah, *al, *bh, *bl;
    cudaGetSymbolAddress((void**)&xh, g_xh); cudaGetSymbolAddress((void**)&xl, g_xl);
    cudaGetSymbolAddress((void**)&ah, g_ah); cudaGetSymbolAddress((void**)&al, g_al);
    cudaGetSymbolAddress((void**)&bh, g_bh); cudaGetSymbolAddress((void**)&bl, g_bl);
    __nv_bfloat16 *w1h, *w1l, *w2h, *w2l, *f1h, *f1l, *f2h, *f2l;
    cudaGetSymbolAddress((void**)&w1h, g_w1h); cudaGetSymbolAddress((void**)&w1l, g_w1l);
    cudaGetSymbolAddress((void**)&w2h, g_w2h); cudaGetSymbolAddress((void**)&w2l, g_w2l);
    cudaGetSymbolAddress((void**)&f1h, g_f1h); cudaGetSymbolAddress((void**)&f1l, g_f1l);
    cudaGetSymbolAddress((void**)&f2h, g_f2h); cudaGetSymbolAddress((void**)&f2l, g_f2l);

    cudaFuncSetAttribute(hmma_gemm, cudaFuncAttributeMaxDynamicSharedMemorySize, GSMEM);
    cudaFuncSetAttribute(flash_kernel, cudaFuncAttributeMaxDynamicSharedMemorySize, FLASH_SMEM);

    // Split input + weights to bf16 hi/lo (weights transposed to [N][K])
    split_k<<<(TOK * 256 + 255) / 256, 256>>>(x_in, xh, xl, TOK * 256);
    for (int p = 0; p < 3; p++) {
        splitT_k<<<(256 * 512 + 255) / 256, 256>>>(W1[p], w1h + p * 512 * 256, w1l + p * 512 * 256, 256, 512);
        splitT_k<<<(512 * 512 + 255) / 256, 256>>>(W2[p], w2h + p * 512 * 512, w2l + p * 512 * 512, 512, 512);
    }
    splitT_k<<<(512 * 1024 + 255) / 256, 256>>>(fW1, f1h, f1l, 512, 1024);
    splitT_k<<<(1024 * 512 + 255) / 256, 256>>>(fW2, f2h, f2l, 1024, 512);

    dim3 gN512(4, 64), gN1024(8, 64);
    float* qkv_out[3] = {pq, pk, pv};

    // Q/K/V two-layer MLPs on tensor cores (HMMA)
    for (int p = 0; p < 3; p++) {
        hmma_gemm<<<gN512, 256, GSMEM>>>(xh, xl, w1h + p * 512 * 256, w1l + p * 512 * 256,
                                         b1[p], (float*)nullptr, ah, al, 512, 256, 1);
        hmma_gemm<<<gN512, 256, GSMEM>>>(ah, al, w2h + p * 512 * 512, w2l + p * 512 * 512,
                                         b2[p], qkv_out[p], (__nv_bfloat16*)nullptr,
                                         (__nv_bfloat16*)nullptr, 512, 512, 0);
    }

    // Attention
    flash_kernel<<<dim3(SEQ / 64, 8, 4), 256, FLASH_SMEM>>>(pq, pk, pv, pctx);

    // x = LN(ctx + q); split for FFN
    ln_kernel<<<TOK, EMB>>>(pctx, pq, ln1g, ln1b, px);
    split_k<<<(TOK * 512 + 255) / 256, 256>>>(px, bh, bl, TOK * 512);

    // FFN
    hmma_gemm<<<gN1024, 256, GSMEM>>>(bh, bl, f1h, f1l, fb1, (float*)nullptr, ah, al, 1024, 512, 1);
    hmma_gemm<<<gN512, 256, GSMEM>>>(ah, al, f2h, f2l, fb2, pctx, (__nv_bfloat16*)nullptr,
                                     (__nv_bfloat16*)nullptr, 512, 1024, 0);

    // out = LN(x + ff)
    ln_kernel<<<TOK, EMB>>>(px, pctx, ln2g, ln2b, out);
}

// round 4
// speedup vs baseline: 4.9894x; 1.9679x over previous
#include <cuda_runtime.h>
#include <cuda_bf16.h>
#include <cstdint>
#include <math.h>

#define TOK 8192
#define EMB 512
#define SEQ 2048

// ---------------------------------------------------------------------------
// Scratch (__device__ globals: no allocs allowed)
// ---------------------------------------------------------------------------
__device__ float g_q[TOK * EMB];      // fp32 q (LN1 residual)
__device__ float g_ctx[TOK * EMB];
__device__ float g_x[TOK * EMB];

// bf16 hi/lo activations
__device__ __nv_bfloat16 g_xh[TOK * 256], g_xl[TOK * 256];
__device__ __nv_bfloat16 g_ah[TOK * 1024], g_al[TOK * 1024];
__device__ __nv_bfloat16 g_bh[TOK * 512],  g_bl[TOK * 512];
__device__ __nv_bfloat16 g_qh[TOK * 512],  g_ql[TOK * 512];
__device__ __nv_bfloat16 g_kh[TOK * 512],  g_kl[TOK * 512];
__device__ __nv_bfloat16 g_vh[TOK * 512],  g_vl[TOK * 512];

// bf16 hi/lo transposed weights, stored [N][K]
__device__ __nv_bfloat16 g_w1h[3][512 * 256], g_w1l[3][512 * 256];
__device__ __nv_bfloat16 g_w2h[3][512 * 512], g_w2l[3][512 * 512];
__device__ __nv_bfloat16 g_f1h[1024 * 512],   g_f1l[1024 * 512];
__device__ __nv_bfloat16 g_f2h[512 * 1024],   g_f2l[512 * 1024];

// ---------------------------------------------------------------------------
// Family-portable PTX helpers
// ---------------------------------------------------------------------------
__device__ __forceinline__ uint32_t smem_u32(const void* p) {
    uint32_t a;
    asm("{ .reg .u64 t; cvta.to.shared.u64 t, %1; cvt.u32.u64 %0, t; }" : "=r"(a) : "l"(p));
    return a;
}
__device__ __forceinline__ void cp16(uint32_t dst, const void* src) {
    asm volatile("cp.async.cg.shared.global [%0], [%1], 16;" :: "r"(dst), "l"(src) : "memory");
}
__device__ __forceinline__ void cp_commit() {
    asm volatile("cp.async.commit_group;" ::: "memory");
}
__device__ __forceinline__ void ldsm_x4(uint32_t* r, uint32_t addr) {
    asm volatile("ldmatrix.sync.aligned.m8n8.x4.shared.b16 {%0,%1,%2,%3}, [%4];"
                 : "=r"(r[0]), "=r"(r[1]), "=r"(r[2]), "=r"(r[3]) : "r"(addr));
}
__device__ __forceinline__ void ldsm_x4_t(uint32_t* r, uint32_t addr) {
    asm volatile("ldmatrix.sync.aligned.m8n8.x4.trans.shared.b16 {%0,%1,%2,%3}, [%4];"
                 : "=r"(r[0]), "=r"(r[1]), "=r"(r[2]), "=r"(r[3]) : "r"(addr));
}
__device__ __forceinline__ void mma16816(float* c, const uint32_t* a, const uint32_t* b) {
    asm volatile("mma.sync.aligned.m16n8k16.row.col.f32.bf16.bf16.f32 "
                 "{%0,%1,%2,%3}, {%4,%5,%6,%7}, {%8,%9}, {%0,%1,%2,%3};"
                 : "+f"(c[0]), "+f"(c[1]), "+f"(c[2]), "+f"(c[3])
                 : "r"(a[0]), "r"(a[1]), "r"(a[2]), "r"(a[3]), "r"(b[0]), "r"(b[1]));
}

// ---------------------------------------------------------------------------
// Precision-split kernels
// ---------------------------------------------------------------------------
__global__ void split_k(const float* __restrict__ X, __nv_bfloat16* __restrict__ h,
                        __nv_bfloat16* __restrict__ l, int n) {
    int i = blockIdx.x * blockDim.x + threadIdx.x;
    if (i < n) {
        float v = X[i];
        __nv_bfloat16 hb = __float2bfloat16(v);
        h[i] = hb;
        l[i] = __float2bfloat16(v - __bfloat162float(hb));
    }
}
__global__ void splitT_k(const float* __restrict__ W, __nv_bfloat16* __restrict__ h,
                         __nv_bfloat16* __restrict__ l, int K, int N) {
    int i = blockIdx.x * blockDim.x + threadIdx.x;
    if (i < K * N) {
        int k = i / N, n = i - k * N;
        float v = W[i];
        __nv_bfloat16 hb = __float2bfloat16(v);
        h[(size_t)n * K + k] = hb;
        l[(size_t)n * K + k] = __float2bfloat16(v - __bfloat162float(hb));
    }
}

// ---------------------------------------------------------------------------
// HMMA bf16x3 GEMM (unchanged from round 3 — proven)
// ---------------------------------------------------------------------------
#define KPAD 40
#define TILE_SM (128 * KPAD)
#define STAGE_SM (4 * TILE_SM)
#define GSMEM (2 * STAGE_SM * 2)

__global__ void __launch_bounds__(256) hmma_gemm(
    const __nv_bfloat16* __restrict__ Ah, const __nv_bfloat16* __restrict__ Al,
    const __nv_bfloat16* __restrict__ Bh, const __nv_bfloat16* __restrict__ Bl,
    const float* __restrict__ bias, float* __restrict__ Cf,
    __nv_bfloat16* __restrict__ Ch, __nv_bfloat16* __restrict__ Cl,
    int N, int K, int relu)
{
    extern __shared__ __nv_bfloat16 sm[];
    const uint32_t smb = smem_u32(sm);
    const int tid = threadIdx.x;
    const int wid = tid >> 5, lane = tid & 31;
    const int bm = blockIdx.y * 128, bn = blockIdx.x * 128;
    const int wm = (wid >> 2) * 64, wn = (wid & 3) * 32;

    float acc[4][4][4];
#pragma unroll
    for (int mt = 0; mt < 4; mt++)
#pragma unroll
        for (int nt = 0; nt < 4; nt++)
#pragma unroll
            for (int r = 0; r < 4; r++) acc[mt][nt][r] = 0.f;

    const int nch = K >> 5;

    auto issue_loads = [&](int ck, int s) {
        const size_t koff = (size_t)ck * 32;
        const __nv_bfloat16* srcs[4] = {
            Ah + (size_t)bm * K + koff, Al + (size_t)bm * K + koff,
            Bh + (size_t)bn * K + koff, Bl + (size_t)bn * K + koff };
#pragma unroll
        for (int t = 0; t < 4; t++) {
#pragma unroll
            for (int i = 0; i < 2; i++) {
                int idx = tid + i * 256;
                int r = idx >> 2, c16 = idx & 3;
                uint32_t dst = smb + (uint32_t)(s * STAGE_SM + t * TILE_SM + r * KPAD + c16 * 8) * 2;
                cp16(dst, srcs[t] + (size_t)r * K + c16 * 8);
            }
        }
        cp_commit();
    };

    issue_loads(0, 0);

    const int arow = (lane & 15);
    const int acol8 = (lane >> 4) * 8;
    const int brow = ((lane >> 4) & 1) * 8 + (lane & 7);
    const int bcol8 = ((lane >> 3) & 1) * 8;

    for (int ck = 0; ck < nch; ck++) {
        const int s = ck & 1;
        if (ck + 1 < nch) {
            issue_loads(ck + 1, s ^ 1);
            asm volatile("cp.async.wait_group 1;" ::: "memory");
        } else {
            asm volatile("cp.async.wait_group 0;" ::: "memory");
        }
        __syncthreads();

        const uint32_t aH = smb + (uint32_t)(s * STAGE_SM + 0 * TILE_SM) * 2;
        const uint32_t aL = smb + (uint32_t)(s * STAGE_SM + 1 * TILE_SM) * 2;
        const uint32_t bH = smb + (uint32_t)(s * STAGE_SM + 2 * TILE_SM) * 2;
        const uint32_t bL = smb + (uint32_t)(s * STAGE_SM + 3 * TILE_SM) * 2;

#pragma unroll
        for (int k16 = 0; k16 < 2; k16++) {
            uint32_t fah[4][4], fal[4][4], fbh[2][4], fbl[2][4];
#pragma unroll
            for (int mt = 0; mt < 4; mt++) {
                uint32_t off = (uint32_t)((wm + mt * 16 + arow) * KPAD + k16 * 16 + acol8) * 2;
                ldsm_x4(fah[mt], aH + off);
                ldsm_x4(fal[mt], aL + off);
            }
#pragma unroll
            for (int p = 0; p < 2; p++) {
                uint32_t off = (uint32_t)((wn + p * 16 + brow) * KPAD + k16 * 16 + bcol8) * 2;
                ldsm_x4(fbh[p], bH + off);
                ldsm_x4(fbl[p], bL + off);
            }
#pragma unroll
            for (int mt = 0; mt < 4; mt++) {
#pragma unroll
                for (int nt = 0; nt < 4; nt++) {
                    const uint32_t* bh2 = &fbh[nt >> 1][(nt & 1) * 2];
                    const uint32_t* bl2 = &fbl[nt >> 1][(nt & 1) * 2];
                    mma16816(acc[mt][nt], fah[mt], bh2);
                    mma16816(acc[mt][nt], fah[mt], bl2);
                    mma16816(acc[mt][nt], fal[mt], bh2);
                }
            }
        }
        __syncthreads();
    }

    const int gid = lane >> 2, tig = lane & 3;
#pragma unroll
    for (int mt = 0; mt < 4; mt++) {
#pragma unroll
        for (int nt = 0; nt < 4; nt++) {
            const int c0 = bn + wn + nt * 8 + tig * 2;
            const float bb0 = __ldg(&bias[c0]), bb1 = __ldg(&bias[c0 + 1]);
#pragma unroll
            for (int half = 0; half < 2; half++) {
                const int r = bm + wm + mt * 16 + gid + half * 8;
                float v0 = acc[mt][nt][half * 2 + 0] + bb0;
                float v1 = acc[mt][nt][half * 2 + 1] + bb1;
                if (relu) { v0 = fmaxf(v0, 0.f); v1 = fmaxf(v1, 0.f); }
                const size_t gi = (size_t)r * N + c0;
                if (Cf) *reinterpret_cast<float2*>(Cf + gi) = make_float2(v0, v1);
                if (Ch) {
                    __nv_bfloat16 h0 = __float2bfloat16(v0);
                    __nv_bfloat16 h1 = __float2bfloat16(v1);
                    __nv_bfloat162 hh; hh.x = h0; hh.y = h1;
                    __nv_bfloat162 ll;
                    ll.x = __float2bfloat16(v0 - __bfloat162float(h0));
                    ll.y = __float2bfloat16(v1 - __bfloat162float(h1));
                    *reinterpret_cast<__nv_bfloat162*>(Ch + gi) = hh;
                    *reinterpret_cast<__nv_bfloat162*>(Cl + gi) = ll;
                }
            }
        }
    }
}

// ---------------------------------------------------------------------------
// HMMA flash attention, bf16x3 for QK^T and PV, fp32 softmax.
// Block = 64 q-rows x 1 head x 1 batch; 4 warps (16 rows each); 32 K-tiles.
// smem: Q hi/lo [64x64] + double-buffered K/V hi/lo [64x64 each], pitch 72.
// ---------------------------------------------------------------------------
#define FPITCH 72
#define FTILE (64 * FPITCH)                 // elems per tile
#define FSTAGE (4 * FTILE)                  // Kh, Kl, Vh, Vl
#define FSMEM ((2 * FTILE + 2 * FSTAGE) * 2)  // bytes = 92160

__global__ void __launch_bounds__(128) flash_hmma(
    const __nv_bfloat16* __restrict__ Qh, const __nv_bfloat16* __restrict__ Ql,
    const __nv_bfloat16* __restrict__ Kh, const __nv_bfloat16* __restrict__ Kl,
    const __nv_bfloat16* __restrict__ Vh, const __nv_bfloat16* __restrict__ Vl,
    float* __restrict__ O)
{
    extern __shared__ __nv_bfloat16 fsm[];
    const uint32_t smb = smem_u32(fsm);
    const int tid = threadIdx.x, wid = tid >> 5, lane = tid & 31;
    const int qt = blockIdx.x, h = blockIdx.y, b = blockIdx.z;
    const int qrow0 = b * SEQ + qt * 64;
    const int col0 = h * 64;
    const float CEXP = 0.044194173824159216f * 1.4426950408889634f;

    // Load Q hi/lo tiles [64 x 64] into smem
#pragma unroll
    for (int i = 0; i < 8; i++) {
        int idx = tid + i * 128;                  // 0..1023
        const __nv_bfloat16* src = (i < 4) ? Qh : Ql;
        int r = (idx >> 3) & 63, ch = idx & 7;
        uint4 v = *reinterpret_cast<const uint4*>(src + (size_t)(qrow0 + r) * EMB + col0 + ch * 8);
        *reinterpret_cast<uint4*>(fsm + (i < 4 ? 0 : FTILE) + r * FPITCH + ch * 8) = v;
    }
    __syncthreads();

    // Q fragments (A operand): 4 k-steps x 4 regs, hi and lo
    const int warpm = wid * 16;
    const int arow = lane & 15, acol8 = (lane >> 4) * 8;
    uint32_t qfh[4][4], qfl[4][4];
#pragma unroll
    for (int kk = 0; kk < 4; kk++) {
        uint32_t off = (uint32_t)((warpm + arow) * FPITCH + kk * 16 + acol8) * 2;
        ldsm_x4(qfh[kk], smb + off);
        ldsm_x4(qfl[kk], smb + (uint32_t)FTILE * 2 + off);
    }

    auto load_kv = [&](int it, int s) {
        const int krow0 = b * SEQ + it * 64;
        const uint32_t stg = (uint32_t)(2 * FTILE + s * FSTAGE);
#pragma unroll
        for (int t = 0; t < 4; t++) {
            const __nv_bfloat16* src = (t == 0) ? Kh : (t == 1) ? Kl : (t == 2) ? Vh : Vl;
#pragma unroll
            for (int i = 0; i < 4; i++) {
                int idx = tid + i * 128;          // 0..511
                int r = idx >> 3, ch = idx & 7;
                uint32_t dst = smb + (stg + (uint32_t)(t * FTILE + r * FPITCH + ch * 8)) * 2;
                cp16(dst, src + (size_t)(krow0 + r) * EMB + col0 + ch * 8);
            }
        }
        cp_commit();
    };

    float m0 = -1e30f, m1 = -1e30f, l0 = 0.f, l1 = 0.f;
    float o[8][4];
#pragma unroll
    for (int nt = 0; nt < 8; nt++)
#pragma unroll
        for (int j = 0; j < 4; j++) o[nt][j] = 0.f;

    const int brow = (lane & 7) + ((lane >> 4) & 1) * 8;   // K (non-trans)
    const int bcol8 = ((lane >> 3) & 1) * 8;
    const int vrow = (lane & 7) + ((lane >> 3) & 1) * 8;   // V (trans)
    const int vcol8 = ((lane >> 4) & 1) * 8;

    load_kv(0, 0);

    for (int it = 0; it < SEQ / 64; it++) {
        const int s = it & 1;
        if (it + 1 < SEQ / 64) {
            load_kv(it + 1, s ^ 1);
            asm volatile("cp.async.wait_group 1;" ::: "memory");
        } else {
            asm volatile("cp.async.wait_group 0;" ::: "memory");
        }
        __syncthreads();

        const uint32_t stg = smb + (uint32_t)(2 * FTILE + s * FSTAGE) * 2;
        const uint32_t kbH = stg, kbL = stg + FTILE * 2;
        const uint32_t vbH = stg + 2 * FTILE * 2, vbL = stg + 3 * FTILE * 2;

        // ---- S = Q K^T (bf16x3) ----
        float sacc[8][4];
#pragma unroll
        for (int nt = 0; nt < 8; nt++)
#pragma unroll
            for (int j = 0; j < 4; j++) sacc[nt][j] = 0.f;

#pragma unroll
        for (int kk = 0; kk < 4; kk++) {
#pragma unroll
            for (int np = 0; np < 4; np++) {
                uint32_t bh[4], bl[4];
                uint32_t off = (uint32_t)((np * 16 + brow) * FPITCH + kk * 16 + bcol8) * 2;
                ldsm_x4(bh, kbH + off);
                ldsm_x4(bl, kbL + off);
                mma16816(sacc[2 * np],     qfh[kk], bh);
                mma16816(sacc[2 * np],     qfh[kk], bl);
                mma16816(sacc[2 * np],     qfl[kk], bh);
                mma16816(sacc[2 * np + 1], qfh[kk], bh + 2);
                mma16816(sacc[2 * np + 1], qfh[kk], bl + 2);
                mma16816(sacc[2 * np + 1], qfl[kk], bh + 2);
            }
        }

        // ---- online softmax ----
        float rmax0 = -1e30f, rmax1 = -1e30f;
#pragma unroll
        for (int nt = 0; nt < 8; nt++) {
            rmax0 = fmaxf(rmax0, fmaxf(sacc[nt][0], sacc[nt][1]));
            rmax1 = fmaxf(rmax1, fmaxf(sacc[nt][2], sacc[nt][3]));
        }
        rmax0 = fmaxf(rmax0, __shfl_xor_sync(0xffffffffu, rmax0, 1));
        rmax0 = fmaxf(rmax0, __shfl_xor_sync(0xffffffffu, rmax0, 2));
        rmax1 = fmaxf(rmax1, __shfl_xor_sync(0xffffffffu, rmax1, 1));
        rmax1 = fmaxf(rmax1, __shfl_xor_sync(0xffffffffu, rmax1, 2));
        const float mn0 = fmaxf(m0, rmax0), mn1 = fmaxf(m1, rmax1);
        const float f0 = exp2f((m0 - mn0) * CEXP), f1 = exp2f((m1 - mn1) * CEXP);

        float rs0 = 0.f, rs1 = 0.f;
        uint32_t pfh[4][4], pfl[4][4];    // A-frags for PV, per 16-key group
#pragma unroll
        for (int np = 0; np < 4; np++) {
#pragma unroll
            for (int half = 0; half < 2; half++) {
                const int nt = 2 * np + half;
                float p0 = exp2f((sacc[nt][0] - mn0) * CEXP);
                float p1 = exp2f((sacc[nt][1] - mn0) * CEXP);
                float p2 = exp2f((sacc[nt][2] - mn1) * CEXP);
                float p3 = exp2f((sacc[nt][3] - mn1) * CEXP);
                rs0 += p0 + p1; rs1 += p2 + p3;
                __nv_bfloat162 h01 = __floats2bfloat162_rn(p0, p1);
                __nv_bfloat162 h23 = __floats2bfloat162_rn(p2, p3);
                __nv_bfloat162 l01 = __floats2bfloat162_rn(p0 - __low2float(h01), p1 - __high2float(h01));
                __nv_bfloat162 l23 = __floats2bfloat162_rn(p2 - __low2float(h23), p3 - __high2float(h23));
                pfh[np][half * 2 + 0] = *reinterpret_cast<uint32_t*>(&h01);
                pfh[np][half * 2 + 1] = *reinterpret_cast<uint32_t*>(&h23);
                pfl[np][half * 2 + 0] = *reinterpret_cast<uint32_t*>(&l01);
                pfl[np][half * 2 + 1] = *reinterpret_cast<uint32_t*>(&l23);
            }
        }
        rs0 += __shfl_xor_sync(0xffffffffu, rs0, 1);
        rs0 += __shfl_xor_sync(0xffffffffu, rs0, 2);
        rs1 += __shfl_xor_sync(0xffffffffu, rs1, 1);
        rs1 += __shfl_xor_sync(0xffffffffu, rs1, 2);
        l0 = l0 * f0 + rs0; m0 = mn0;
        l1 = l1 * f1 + rs1; m1 = mn1;
#pragma unroll
        for (int nt = 0; nt < 8; nt++) {
            o[nt][0] *= f0; o[nt][1] *= f0;
            o[nt][2] *= f1; o[nt][3] *= f1;
        }

        // ---- O += P V (bf16x3) ----
#pragma unroll
        for (int kk = 0; kk < 4; kk++) {
#pragma unroll
            for (int dp = 0; dp < 4; dp++) {
                uint32_t bh[4], bl[4];
                uint32_t off = (uint32_t)((kk * 16 + vrow) * FPITCH + dp * 16 + vcol8) * 2;
                ldsm_x4_t(bh, vbH + off);
                ldsm_x4_t(bl, vbL + off);
                mma16816(o[2 * dp],     pfh[kk], bh);
                mma16816(o[2 * dp],     pfh[kk], bl);
                mma16816(o[2 * dp],     pfl[kk], bh);
                mma16816(o[2 * dp + 1], pfh[kk], bh + 2);
                mma16816(o[2 * dp + 1], pfh[kk], bl + 2);
                mma16816(o[2 * dp + 1], pfl[kk], bh + 2);
            }
        }
        __syncthreads();
    }

    // ---- epilogue ----
    const float inv0 = 1.f / l0, inv1 = 1.f / l1;
    const int r0 = qrow0 + warpm + (lane >> 2), r1 = r0 + 8;
#pragma unroll
    for (int nt = 0; nt < 8; nt++) {
        const int c = col0 + nt * 8 + (lane & 3) * 2;
        *reinterpret_cast<float2*>(O + (size_t)r0 * EMB + c) = make_float2(o[nt][0] * inv0, o[nt][1] * inv0);
        *reinterpret_cast<float2*>(O + (size_t)r1 * EMB + c) = make_float2(o[nt][2] * inv1, o[nt][3] * inv1);
    }
}

// ---------------------------------------------------------------------------
// Fused residual + LayerNorm (+ optional hi/lo bf16 split of output)
// ---------------------------------------------------------------------------
__global__ void ln_kernel(const float* __restrict__ A, const float* __restrict__ Bres,
                          const float* __restrict__ g, const float* __restrict__ beta,
                          float* __restrict__ out,
                          __nv_bfloat16* __restrict__ oh, __nv_bfloat16* __restrict__ ol)
{
    const int row = blockIdx.x;
    const int t = threadIdx.x;  // 512
    float v = A[(size_t)row * EMB + t] + Bres[(size_t)row * EMB + t];

    __shared__ float rsum[16], rsq[16];
    float s1 = v, s2 = v * v;
#pragma unroll
    for (int off = 16; off; off >>= 1) {
        s1 += __shfl_xor_sync(0xffffffffu, s1, off);
        s2 += __shfl_xor_sync(0xffffffffu, s2, off);
    }
    if ((t & 31) == 0) { rsum[t >> 5] = s1; rsq[t >> 5] = s2; }
    __syncthreads();
    if (t < 32) {
        s1 = (t < 16) ? rsum[t] : 0.f;
        s2 = (t < 16) ? rsq[t] : 0.f;
#pragma unroll
        for (int off = 8; off; off >>= 1) {
            s1 += __shfl_xor_sync(0xffffffffu, s1, off);
            s2 += __shfl_xor_sync(0xffffffffu, s2, off);
        }
        if (t == 0) { rsum[0] = s1; rsq[0] = s2; }
    }
    __syncthreads();
    float mu = rsum[0] * (1.f / EMB);
    float var = rsq[0] * (1.f / EMB) - mu * mu;
    float inv = rsqrtf(var + 1e-5f);
    float y = (v - mu) * inv * g[t] + beta[t];
    out[(size_t)row * EMB + t] = y;
    if (oh) {
        __nv_bfloat16 hb = __float2bfloat16(y);
        oh[(size_t)row * EMB + t] = hb;
        ol[(size_t)row * EMB + t] = __float2bfloat16(y - __bfloat162float(hb));
    }
}

// ---------------------------------------------------------------------------
// Launch
// ---------------------------------------------------------------------------
extern "C" void kernel_launch(void* const* d_in, const int* in_sizes, int n_in,
                              void* d_out, int out_size)
{
    (void)in_sizes; (void)n_in; (void)out_size;

    const float* x_in = (const float*)d_in[0];
    const float* W1[3] = {(const float*)d_in[1], (const float*)d_in[5], (const float*)d_in[9]};
    const float* b1[3] = {(const float*)d_in[2], (const float*)d_in[6], (const float*)d_in[10]};
    const float* W2[3] = {(const float*)d_in[3], (const float*)d_in[7], (const float*)d_in[11]};
    const float* b2[3] = {(const float*)d_in[4], (const float*)d_in[8], (const float*)d_in[12]};
    const float* fW1 = (const float*)d_in[13]; const float* fb1 = (const float*)d_in[14];
    const float* fW2 = (const float*)d_in[15]; const float* fb2 = (const float*)d_in[16];
    const float* ln1g = (const float*)d_in[17]; const float* ln1b = (const float*)d_in[18];
    const float* ln2g = (const float*)d_in[19]; const float* ln2b = (const float*)d_in[20];
    float* out = (float*)d_out;

    float *pq, *pctx, *px;
    cudaGetSymbolAddress((void**)&pq, g_q);
    cudaGetSymbolAddress((void**)&pctx, g_ctx);
    cudaGetSymbolAddress((void**)&px, g_x);
    __nv_bfloat16 *xh, *xl, *ah, *al, *bh, *bl;
    __nv_bfloat16 *qh, *ql, *kh, *kl, *vh, *vl;
    cudaGetSymbolAddress((void**)&xh, g_xh); cudaGetSymbolAddress((void**)&xl, g_xl);
    cudaGetSymbolAddress((void**)&ah, g_ah); cudaGetSymbolAddress((void**)&al, g_al);
    cudaGetSymbolAddress((void**)&bh, g_bh); cudaGetSymbolAddress((void**)&bl, g_bl);
    cudaGetSymbolAddress((void**)&qh, g_qh); cudaGetSymbolAddress((void**)&ql, g_ql);
    cudaGetSymbolAddress((void**)&kh, g_kh); cudaGetSymbolAddress((void**)&kl, g_kl);
    cudaGetSymbolAddress((void**)&vh, g_vh); cudaGetSymbolAddress((void**)&vl, g_vl);
    __nv_bfloat16 *w1h, *w1l, *w2h, *w2l, *f1h, *f1l, *f2h, *f2l;
    cudaGetSymbolAddress((void**)&w1h, g_w1h); cudaGetSymbolAddress((void**)&w1l, g_w1l);
    cudaGetSymbolAddress((void**)&w2h, g_w2h); cudaGetSymbolAddress((void**)&w2l, g_w2l);
    cudaGetSymbolAddress((void**)&f1h, g_f1h); cudaGetSymbolAddress((void**)&f1l, g_f1l);
    cudaGetSymbolAddress((void**)&f2h, g_f2h); cudaGetSymbolAddress((void**)&f2l, g_f2l);

    cudaFuncSetAttribute(hmma_gemm, cudaFuncAttributeMaxDynamicSharedMemorySize, GSMEM);
    cudaFuncSetAttribute(flash_hmma, cudaFuncAttributeMaxDynamicSharedMemorySize, FSMEM);

    // Split input + weights to bf16 hi/lo
    split_k<<<(TOK * 256 + 255) / 256, 256>>>(x_in, xh, xl, TOK * 256);
    for (int p = 0; p < 3; p++) {
        splitT_k<<<(256 * 512 + 255) / 256, 256>>>(W1[p], w1h + p * 512 * 256, w1l + p * 512 * 256, 256, 512);
        splitT_k<<<(512 * 512 + 255) / 256, 256>>>(W2[p], w2h + p * 512 * 512, w2l + p * 512 * 512, 512, 512);
    }
    splitT_k<<<(512 * 1024 + 255) / 256, 256>>>(fW1, f1h, f1l, 512, 1024);
    splitT_k<<<(1024 * 512 + 255) / 256, 256>>>(fW2, f2h, f2l, 1024, 512);

    dim3 gN512(4, 64), gN1024(8, 64);

    // Q/K/V MLPs; second GEMM emits bf16 hi/lo directly (q also fp32 for residual)
    __nv_bfloat16* outH[3] = {qh, kh, vh};
    __nv_bfloat16* outL[3] = {ql, kl, vl};
    float* outF[3] = {pq, nullptr, nullptr};
    for (int p = 0; p < 3; p++) {
        hmma_gemm<<<gN512, 256, GSMEM>>>(xh, xl, w1h + p * 512 * 256, w1l + p * 512 * 256,
                                         b1[p], (float*)nullptr, ah, al, 512, 256, 1);
        hmma_gemm<<<gN512, 256, GSMEM>>>(ah, al, w2h + p * 512 * 512, w2l + p * 512 * 512,
                                         b2[p], outF[p], outH[p], outL[p], 512, 512, 0);
    }

    // Attention (HMMA flash)
    flash_hmma<<<dim3(SEQ / 64, 8, 4), 128, FSMEM>>>(qh, ql, kh, kl, vh, vl, pctx);

    // x = LN(ctx + q), fused hi/lo split for FFN
    ln_kernel<<<TOK, EMB>>>(pctx, pq, ln1g, ln1b, px, bh, bl);

    // FFN
    hmma_gemm<<<gN1024, 256, GSMEM>>>(bh, bl, f1h, f1l, fb1, (float*)nullptr, ah, al, 1024, 512, 1);
    hmma_gemm<<<gN512, 256, GSMEM>>>(ah, al, f2h, f2l, fb2, pctx, (__nv_bfloat16*)nullptr,
                                     (__nv_bfloat16*)nullptr, 512, 1024, 0);

    // out = LN(x + ff)
    ln_kernel<<<TOK, EMB>>>(px, pctx, ln2g, ln2b, out, (__nv_bfloat16*)nullptr, (__nv_bfloat16*)nullptr);
}